// round 8
// baseline (speedup 1.0000x reference)
#include <cuda_runtime.h>
#include <cuda_bf16.h>
#include <mma.h>
#include <cstdint>
#include <math.h>

using namespace nvcuda;

// Problem constants
#define BZ   8
#define DI   256
#define DS   512
#define DO   256
#define LL   4096
#define NCH  32
#define CLEN 128
#define LANES (BZ*DS)

// ---------------- scratch ----------------
__device__ float g_Bu[(size_t)LL * BZ * DS];         // (l, b, s) fp32 (Bu; scan reads)
__device__ float g_last[NCH * LANES];
__device__ float g_carry[NCH * LANES];

// pre-split bf16 operands
__device__ __nv_bfloat16 g_uhi[(size_t)BZ * LL * DI];   // [b][l][i]  (K-major u)
__device__ __nv_bfloat16 g_ulo[(size_t)BZ * LL * DI];
__device__ __nv_bfloat16 g_xhi[(size_t)LL * BZ * DS];   // [l][b][s]  (K-major x)
__device__ __nv_bfloat16 g_xlo[(size_t)LL * BZ * DS];

// split weights (bf16 hi/lo), row-major [n][k] like the fp32 originals
#define WB_OFF 0
#define WC_OFF (512*256)
#define WD_OFF (WC_OFF + 256*512)
#define WTOT   (WD_OFF + 256*256)
__device__ __nv_bfloat16 g_whi[WTOT];
__device__ __nv_bfloat16 g_wlo[WTOT];

__device__ __forceinline__ float softplus_f(float x) {
    return fmaxf(x, 0.f) + log1pf(expf(-fabsf(x)));
}

// ---------------- prep: weight split ----------------
__global__ void prep_kernel(const float* __restrict__ Bm, const float* __restrict__ Cm,
                            const float* __restrict__ Dm) {
    int i = blockIdx.x * 256 + threadIdx.x;
    if (i >= WTOT) return;
    float v = (i < WC_OFF) ? Bm[i] : (i < WD_OFF ? Cm[i - WC_OFF] : Dm[i - WD_OFF]);
    __nv_bfloat16 h = __float2bfloat16(v);
    g_whi[i] = h;
    g_wlo[i] = __float2bfloat16(v - __bfloat162float(h));
}

// ---------------- usplit: u[b][i][l] -> bf16 hi/lo [b][l][i] (32x32 tile transpose) ----
__global__ __launch_bounds__(256) void usplit_kernel(const float* __restrict__ u) {
    __shared__ float t[32][33];
    const int tx = threadIdx.x & 31, ty = threadIdx.x >> 5;
    const int l0 = blockIdx.x * 32, i0 = blockIdx.y * 32, b = blockIdx.z;

    #pragma unroll
    for (int q = 0; q < 4; q++)
        t[ty + 8 * q][tx] = u[((size_t)b * DI + i0 + ty + 8 * q) * LL + l0 + tx];
    __syncthreads();

    #pragma unroll
    for (int q = 0; q < 4; q++) {
        const int l = l0 + ty + 8 * q;
        float v = t[tx][ty + 8 * q];
        __nv_bfloat16 h = __float2bfloat16(v);
        size_t idx = ((size_t)b * LL + l) * DI + i0 + tx;
        g_uhi[idx] = h;
        g_ulo[idx] = __float2bfloat16(v - __bfloat162float(h));
    }
}

// ---------------- GEMM1: g_Bu[l][b][s] = u(b,:,l) . Bm(s,:) ----------------
// No smem, no syncs: fragments straight from pre-split global bf16.
__global__ __launch_bounds__(256) void gemm1_wmma(int dummy) {
    const int wid = threadIdx.x >> 5;
    const int l0 = blockIdx.x * 128, s0 = blockIdx.y * 64, b = blockIdx.z;
    const int wm = wid & 3, wn = wid >> 2;          // 4 x 2 warps, warp tile 32x32

    wmma::fragment<wmma::accumulator, 16, 16, 16, float> acc[2][2];
    #pragma unroll
    for (int i = 0; i < 2; i++)
        #pragma unroll
        for (int j = 0; j < 2; j++) wmma::fill_fragment(acc[i][j], 0.f);

    const size_t aRow0 = ((size_t)b * LL + l0 + wm * 32) * DI;
    const size_t bRow0 = (size_t)(s0 + wn * 32) * DI;

    #pragma unroll 4
    for (int k = 0; k < DI / 16; k++) {
        wmma::fragment<wmma::matrix_a, 16, 16, 16, __nv_bfloat16, wmma::row_major> ah[2], al[2];
        wmma::fragment<wmma::matrix_b, 16, 16, 16, __nv_bfloat16, wmma::col_major> bh[2], bl[2];
        #pragma unroll
        for (int i = 0; i < 2; i++) {
            wmma::load_matrix_sync(ah[i], g_uhi + aRow0 + (size_t)(i * 16) * DI + k * 16, DI);
            wmma::load_matrix_sync(al[i], g_ulo + aRow0 + (size_t)(i * 16) * DI + k * 16, DI);
        }
        #pragma unroll
        for (int j = 0; j < 2; j++) {
            wmma::load_matrix_sync(bh[j], g_whi + WB_OFF + bRow0 + (size_t)(j * 16) * DI + k * 16, DI);
            wmma::load_matrix_sync(bl[j], g_wlo + WB_OFF + bRow0 + (size_t)(j * 16) * DI + k * 16, DI);
        }
        #pragma unroll
        for (int i = 0; i < 2; i++)
            #pragma unroll
            for (int j = 0; j < 2; j++) {
                wmma::mma_sync(acc[i][j], ah[i], bh[j], acc[i][j]);
                wmma::mma_sync(acc[i][j], ah[i], bl[j], acc[i][j]);
                wmma::mma_sync(acc[i][j], al[i], bh[j], acc[i][j]);
            }
    }

    #pragma unroll
    for (int i = 0; i < 2; i++)
        #pragma unroll
        for (int j = 0; j < 2; j++) {
            float* out = g_Bu + (size_t)(l0 + wm * 32 + i * 16) * (BZ * DS)
                              + (size_t)b * DS + s0 + wn * 32 + j * 16;
            wmma::store_matrix_sync(out, acc[i][j], BZ * DS, wmma::mem_row_major);
        }
}

// ---------------- GEMM2: Y[b][o][l] = C.x + D.u ----------------
__global__ __launch_bounds__(256) void gemm2_wmma(float* __restrict__ Y) {
    __shared__ float stg[128 * 72];                  // epilogue transpose, 36864 B
    const int tid = threadIdx.x, wid = tid >> 5;
    const int l0 = blockIdx.x * 128, o0 = blockIdx.y * 64, b = blockIdx.z;
    const int wm = wid & 3, wn = wid >> 2;

    wmma::fragment<wmma::accumulator, 16, 16, 16, float> acc[2][2];
    #pragma unroll
    for (int i = 0; i < 2; i++)
        #pragma unroll
        for (int j = 0; j < 2; j++) wmma::fill_fragment(acc[i][j], 0.f);

    // ---- Phase 1: K over DS; A = x split [l][b][s], ldm = BZ*DS ----
    {
        const size_t aRow0 = ((size_t)(l0 + wm * 32) * BZ + b) * DS;
        const size_t bRow0 = (size_t)(o0 + wn * 32) * DS;
        #pragma unroll 4
        for (int k = 0; k < DS / 16; k++) {
            wmma::fragment<wmma::matrix_a, 16, 16, 16, __nv_bfloat16, wmma::row_major> ah[2], al[2];
            wmma::fragment<wmma::matrix_b, 16, 16, 16, __nv_bfloat16, wmma::col_major> bh[2], bl[2];
            #pragma unroll
            for (int i = 0; i < 2; i++) {
                wmma::load_matrix_sync(ah[i], g_xhi + aRow0 + (size_t)(i * 16) * (BZ * DS) + k * 16, BZ * DS);
                wmma::load_matrix_sync(al[i], g_xlo + aRow0 + (size_t)(i * 16) * (BZ * DS) + k * 16, BZ * DS);
            }
            #pragma unroll
            for (int j = 0; j < 2; j++) {
                wmma::load_matrix_sync(bh[j], g_whi + WC_OFF + bRow0 + (size_t)(j * 16) * DS + k * 16, DS);
                wmma::load_matrix_sync(bl[j], g_wlo + WC_OFF + bRow0 + (size_t)(j * 16) * DS + k * 16, DS);
            }
            #pragma unroll
            for (int i = 0; i < 2; i++)
                #pragma unroll
                for (int j = 0; j < 2; j++) {
                    wmma::mma_sync(acc[i][j], ah[i], bh[j], acc[i][j]);
                    wmma::mma_sync(acc[i][j], ah[i], bl[j], acc[i][j]);
                    wmma::mma_sync(acc[i][j], al[i], bh[j], acc[i][j]);
                }
        }
    }

    // ---- Phase 2: K over DI; A = u split [b][l][i], ldm = DI ----
    {
        const size_t aRow0 = ((size_t)b * LL + l0 + wm * 32) * DI;
        const size_t bRow0 = (size_t)(o0 + wn * 32) * DI;
        #pragma unroll 4
        for (int k = 0; k < DI / 16; k++) {
            wmma::fragment<wmma::matrix_a, 16, 16, 16, __nv_bfloat16, wmma::row_major> ah[2], al[2];
            wmma::fragment<wmma::matrix_b, 16, 16, 16, __nv_bfloat16, wmma::col_major> bh[2], bl[2];
            #pragma unroll
            for (int i = 0; i < 2; i++) {
                wmma::load_matrix_sync(ah[i], g_uhi + aRow0 + (size_t)(i * 16) * DI + k * 16, DI);
                wmma::load_matrix_sync(al[i], g_ulo + aRow0 + (size_t)(i * 16) * DI + k * 16, DI);
            }
            #pragma unroll
            for (int j = 0; j < 2; j++) {
                wmma::load_matrix_sync(bh[j], g_whi + WD_OFF + bRow0 + (size_t)(j * 16) * DI + k * 16, DI);
                wmma::load_matrix_sync(bl[j], g_wlo + WD_OFF + bRow0 + (size_t)(j * 16) * DI + k * 16, DI);
            }
            #pragma unroll
            for (int i = 0; i < 2; i++)
                #pragma unroll
                for (int j = 0; j < 2; j++) {
                    wmma::mma_sync(acc[i][j], ah[i], bh[j], acc[i][j]);
                    wmma::mma_sync(acc[i][j], ah[i], bl[j], acc[i][j]);
                    wmma::mma_sync(acc[i][j], al[i], bh[j], acc[i][j]);
                }
        }
    }

    // ---- epilogue: acc (m=l, n=o) -> transpose via smem -> Y[b][o][l] ----
    #pragma unroll
    for (int i = 0; i < 2; i++)
        #pragma unroll
        for (int j = 0; j < 2; j++) {
            float* sp = stg + (size_t)(wm * 32 + i * 16) * 72 + wn * 32 + j * 16;
            wmma::store_matrix_sync(sp, acc[i][j], 72, wmma::mem_row_major);
        }
    __syncthreads();
    {
        const int o = tid >> 2;                      // 0..63
        const int lseg = (tid & 3) * 32;
        float* yp = Y + ((size_t)b * DO + o0 + o) * LL + l0 + lseg;
        const float* sp = stg + (size_t)lseg * 72 + o;
        #pragma unroll
        for (int q = 0; q < 8; q++) {
            float4 v = make_float4(sp[(q * 4 + 0) * 72], sp[(q * 4 + 1) * 72],
                                   sp[(q * 4 + 2) * 72], sp[(q * 4 + 3) * 72]);
            *(float4*)(yp + q * 4) = v;
        }
    }
}

// ---------------- scan ----------------
__global__ __launch_bounds__(256) void scanA_kernel(const float* __restrict__ Aun) {
    const int t = blockIdx.x * 256 + threadIdx.x;
    const int lane = t & (LANES - 1);
    const int c = t >> 12;
    const int s = lane & (DS - 1);
    const float A = -softplus_f(Aun[s]);
    const float* g = g_Bu + (size_t)(c * CLEN) * LANES + lane;
    float x = 0.f;
    #pragma unroll 8
    for (int j = 0; j < CLEN; j++) x = fmaf(A, x, g[(size_t)j * LANES]);
    g_last[t] = x;
}

__global__ __launch_bounds__(256) void scanB_kernel(const float* __restrict__ Aun,
                                                    const float* __restrict__ h0) {
    const int lane = blockIdx.x * 256 + threadIdx.x;
    const int s = lane & (DS - 1);
    const float A = -softplus_f(Aun[s]);
    float Ap = A;
    #pragma unroll
    for (int i = 0; i < 7; i++) Ap *= Ap;
    float h = h0[s];
    #pragma unroll
    for (int c = 0; c < NCH; c++) {
        g_carry[c * LANES + lane] = h;
        h = fmaf(Ap, h, g_last[c * LANES + lane]);
    }
}

// scanC: recompute chunk scan with correct carry; emit bf16 hi/lo split of x directly.
__global__ __launch_bounds__(256) void scanC_kernel(const float* __restrict__ Aun) {
    const int t = blockIdx.x * 256 + threadIdx.x;
    const int lane = t & (LANES - 1);
    const int c = t >> 12;
    const int s = lane & (DS - 1);
    const float A = -softplus_f(Aun[s]);
    float x = g_carry[t];
    const float* g = g_Bu + (size_t)(c * CLEN) * LANES + lane;
    __nv_bfloat16* xh = g_xhi + (size_t)(c * CLEN) * LANES + lane;
    __nv_bfloat16* xl = g_xlo + (size_t)(c * CLEN) * LANES + lane;
    #pragma unroll 4
    for (int j = 0; j < CLEN; j++) {
        x = fmaf(A, x, g[(size_t)j * LANES]);
        __nv_bfloat16 h = __float2bfloat16(x);
        xh[(size_t)j * LANES] = h;
        xl[(size_t)j * LANES] = __float2bfloat16(x - __bfloat162float(h));
    }
}

// ---------------- launch ----------------
extern "C" void kernel_launch(void* const* d_in, const int* in_sizes, int n_in,
                              void* d_out, int out_size) {
    const float* u   = (const float*)d_in[0];
    const float* Aun = (const float*)d_in[1];
    const float* Bm  = (const float*)d_in[2];
    const float* Cm  = (const float*)d_in[3];
    const float* Dm  = (const float*)d_in[4];
    const float* h0  = (const float*)d_in[5];
    float* Y = (float*)d_out;

    prep_kernel<<<(WTOT + 255) / 256, 256>>>(Bm, Cm, Dm);

    dim3 gu(LL / 32, DI / 32, BZ);
    usplit_kernel<<<gu, 256>>>(u);

    dim3 g1(LL / 128, DS / 64, BZ);
    gemm1_wmma<<<g1, 256>>>(0);

    scanA_kernel<<<(NCH * LANES) / 256, 256>>>(Aun);
    scanB_kernel<<<LANES / 256, 256>>>(Aun, h0);
    scanC_kernel<<<(NCH * LANES) / 256, 256>>>(Aun);

    dim3 g2(LL / 128, DO / 64, BZ);
    gemm2_wmma<<<g2, 256>>>(Y);
}

// round 9
// speedup vs baseline: 2.7599x; 2.7599x over previous
#include <cuda_runtime.h>
#include <cuda_bf16.h>
#include <mma.h>
#include <cstdint>
#include <math.h>

using namespace nvcuda;

// Problem constants
#define BZ   8
#define DI   256
#define DS   512
#define DO   256
#define LL   4096
#define NCH  32
#define CLEN 128
#define LANES (BZ*DS)

// ---------------- scratch ----------------
__device__ float g_Bu[(size_t)LL * BZ * DS];            // (l, b, s) fp32
__device__ float g_last[NCH * LANES];
__device__ float g_carry[NCH * LANES];

// pre-split bf16 operands
__device__ __nv_bfloat16 g_uhi[(size_t)BZ * LL * DI];   // [b][l][i]
__device__ __nv_bfloat16 g_ulo[(size_t)BZ * LL * DI];
__device__ __nv_bfloat16 g_xhi[(size_t)LL * BZ * DS];   // [l][b][s]
__device__ __nv_bfloat16 g_xlo[(size_t)LL * BZ * DS];

// split weights, row-major [n][k]
#define WB_OFF 0
#define WC_OFF (512*256)
#define WD_OFF (WC_OFF + 256*512)
#define WTOT   (WD_OFF + 256*256)
__device__ __nv_bfloat16 g_whi[WTOT];
__device__ __nv_bfloat16 g_wlo[WTOT];

__device__ __forceinline__ float softplus_f(float x) {
    return fmaxf(x, 0.f) + log1pf(expf(-fabsf(x)));
}

// ---------------- cp.async helpers ----------------
__device__ __forceinline__ void cp16(uint32_t saddr, const void* g) {
    asm volatile("cp.async.cg.shared.global [%0], [%1], 16;" :: "r"(saddr), "l"(g));
}
#define CP_COMMIT() asm volatile("cp.async.commit_group;" ::: "memory")
#define CP_WAIT1()  asm volatile("cp.async.wait_group 1;" ::: "memory")
#define CP_WAIT0()  asm volatile("cp.async.wait_group 0;" ::: "memory")

// ---------------- smem layout ----------------
#define KC 32
#define LDS_T 40                         // padded ld (elements) for 128x32 bf16 tiles
#define ST_A_HI 0
#define ST_A_LO 10240
#define ST_B_HI 20480
#define ST_B_LO 30720
#define STAGE_BYTES 40960
#define SMEM_BYTES (2 * STAGE_BYTES)     // 81920

// Copy one 128-row x 32-col bf16 half-tile into padded smem (rows 64B each).
__device__ __forceinline__ void load_half(uint32_t sbase, const __nv_bfloat16* __restrict__ src,
                                          size_t gbase, int gstride, int tid) {
    const int row = tid >> 1, seg = tid & 1;
    const uint32_t sa = sbase + row * (LDS_T * 2) + seg * 32;
    const __nv_bfloat16* gp = src + gbase + (size_t)row * gstride + seg * 16;
    cp16(sa, gp);
    cp16(sa + 16, gp + 8);
}

// ---------------- prep: weight split ----------------
__global__ void prep_kernel(const float* __restrict__ Bm, const float* __restrict__ Cm,
                            const float* __restrict__ Dm) {
    int i = blockIdx.x * 256 + threadIdx.x;
    if (i >= WTOT) return;
    float v = (i < WC_OFF) ? Bm[i] : (i < WD_OFF ? Cm[i - WC_OFF] : Dm[i - WD_OFF]);
    __nv_bfloat16 h = __float2bfloat16(v);
    g_whi[i] = h;
    g_wlo[i] = __float2bfloat16(v - __bfloat162float(h));
}

// ---------------- usplit: u[b][i][l] -> bf16 hi/lo [b][l][i] ----------------
__global__ __launch_bounds__(256) void usplit_kernel(const float* __restrict__ u) {
    __shared__ float t[32][33];
    const int tx = threadIdx.x & 31, ty = threadIdx.x >> 5;
    const int l0 = blockIdx.x * 32, i0 = blockIdx.y * 32, b = blockIdx.z;
    #pragma unroll
    for (int q = 0; q < 4; q++)
        t[ty + 8 * q][tx] = u[((size_t)b * DI + i0 + ty + 8 * q) * LL + l0 + tx];
    __syncthreads();
    #pragma unroll
    for (int q = 0; q < 4; q++) {
        const int l = l0 + ty + 8 * q;
        float v = t[tx][ty + 8 * q];
        __nv_bfloat16 h = __float2bfloat16(v);
        size_t idx = ((size_t)b * LL + l) * DI + i0 + tx;
        g_uhi[idx] = h;
        g_ulo[idx] = __float2bfloat16(v - __bfloat162float(h));
    }
}

// ---------------- GEMM compute body (shared by both GEMMs) ----------------
#define COMPUTE_CHUNK(sm)                                                                 \
    do {                                                                                  \
        __nv_bfloat16* Ah = (__nv_bfloat16*)((sm) + ST_A_HI);                             \
        __nv_bfloat16* Al = (__nv_bfloat16*)((sm) + ST_A_LO);                             \
        __nv_bfloat16* Bh = (__nv_bfloat16*)((sm) + ST_B_HI);                             \
        __nv_bfloat16* Bl = (__nv_bfloat16*)((sm) + ST_B_LO);                             \
        _Pragma("unroll")                                                                 \
        for (int ks = 0; ks < KC; ks += 16) {                                             \
            wmma::fragment<wmma::matrix_a, 16, 16, 16, __nv_bfloat16, wmma::row_major>    \
                ah[2], al[2];                                                             \
            _Pragma("unroll")                                                             \
            for (int i = 0; i < 2; i++) {                                                 \
                wmma::load_matrix_sync(ah[i], Ah + (wm * 32 + i * 16) * LDS_T + ks, LDS_T);\
                wmma::load_matrix_sync(al[i], Al + (wm * 32 + i * 16) * LDS_T + ks, LDS_T);\
            }                                                                             \
            _Pragma("unroll")                                                             \
            for (int j = 0; j < 4; j++) {                                                 \
                wmma::fragment<wmma::matrix_b, 16, 16, 16, __nv_bfloat16, wmma::col_major>\
                    bh, bl;                                                               \
                wmma::load_matrix_sync(bh, Bh + (wn * 64 + j * 16) * LDS_T + ks, LDS_T);  \
                wmma::load_matrix_sync(bl, Bl + (wn * 64 + j * 16) * LDS_T + ks, LDS_T);  \
                _Pragma("unroll")                                                         \
                for (int i = 0; i < 2; i++) {                                             \
                    wmma::mma_sync(acc[i][j], ah[i], bh, acc[i][j]);                      \
                    wmma::mma_sync(acc[i][j], ah[i], bl, acc[i][j]);                      \
                    wmma::mma_sync(acc[i][j], al[i], bh, acc[i][j]);                      \
                }                                                                         \
            }                                                                             \
        }                                                                                 \
    } while (0)

// ---------------- GEMM1: g_Bu[l][b][s] = u . B^T ----------------
__global__ __launch_bounds__(256) void gemm1_wmma(int dummy) {
    extern __shared__ char smem[];
    const uint32_t sb = (uint32_t)__cvta_generic_to_shared(smem);
    const int tid = threadIdx.x, wid = tid >> 5;
    const int l0 = blockIdx.x * 128, n0 = blockIdx.y * 128, b = blockIdx.z;
    const int wm = wid & 3, wn = wid >> 2;

    wmma::fragment<wmma::accumulator, 16, 16, 16, float> acc[2][4];
    #pragma unroll
    for (int i = 0; i < 2; i++)
        #pragma unroll
        for (int j = 0; j < 4; j++) wmma::fill_fragment(acc[i][j], 0.f);

    const size_t aB = ((size_t)b * LL + l0) * DI;
    const size_t bB = (size_t)n0 * DI;
    const int NC = DI / KC;   // 8

    // prologue
    {
        load_half(sb + ST_A_HI, g_uhi, aB, DI, tid);
        load_half(sb + ST_A_LO, g_ulo, aB, DI, tid);
        load_half(sb + ST_B_HI, g_whi + WB_OFF, bB, DI, tid);
        load_half(sb + ST_B_LO, g_wlo + WB_OFF, bB, DI, tid);
        CP_COMMIT();
    }
    for (int c = 0; c < NC; c++) {
        if (c + 1 < NC) {
            uint32_t st = sb + ((c + 1) & 1) * STAGE_BYTES;
            load_half(st + ST_A_HI, g_uhi, aB + (c + 1) * KC, DI, tid);
            load_half(st + ST_A_LO, g_ulo, aB + (c + 1) * KC, DI, tid);
            load_half(st + ST_B_HI, g_whi + WB_OFF, bB + (c + 1) * KC, DI, tid);
            load_half(st + ST_B_LO, g_wlo + WB_OFF, bB + (c + 1) * KC, DI, tid);
            CP_COMMIT();
            CP_WAIT1();
        } else {
            CP_WAIT0();
        }
        __syncthreads();
        char* sm = smem + (c & 1) * STAGE_BYTES;
        COMPUTE_CHUNK(sm);
        __syncthreads();
    }

    #pragma unroll
    for (int i = 0; i < 2; i++)
        #pragma unroll
        for (int j = 0; j < 4; j++) {
            float* out = g_Bu + (size_t)(l0 + wm * 32 + i * 16) * (BZ * DS)
                              + (size_t)b * DS + n0 + wn * 64 + j * 16;
            wmma::store_matrix_sync(out, acc[i][j], BZ * DS, wmma::mem_row_major);
        }
}

// ---------------- GEMM2: Y[b][o][l] = C.x + D.u (unified K = 512 + 256) ------
__global__ __launch_bounds__(256) void gemm2_wmma(float* __restrict__ Y) {
    extern __shared__ char smem[];
    const uint32_t sb = (uint32_t)__cvta_generic_to_shared(smem);
    const int tid = threadIdx.x, wid = tid >> 5;
    const int l0 = blockIdx.x * 128, o0 = blockIdx.y * 128, b = blockIdx.z;
    const int wm = wid & 3, wn = wid >> 2;

    wmma::fragment<wmma::accumulator, 16, 16, 16, float> acc[2][4];
    #pragma unroll
    for (int i = 0; i < 2; i++)
        #pragma unroll
        for (int j = 0; j < 4; j++) wmma::fill_fragment(acc[i][j], 0.f);

    const size_t aX = ((size_t)l0 * BZ + b) * DS;    // x base, row stride BZ*DS
    const size_t aU = ((size_t)b * LL + l0) * DI;    // u base, row stride DI
    const size_t bC = (size_t)o0 * DS;
    const size_t bD = (size_t)o0 * DI;
    const int NC1 = DS / KC;                         // 16
    const int NC = NC1 + DI / KC;                    // 24

    // chunk issuer
    auto issue = [&](int c, uint32_t st) {
        if (c < NC1) {
            load_half(st + ST_A_HI, g_xhi, aX + c * KC, BZ * DS, tid);
            load_half(st + ST_A_LO, g_xlo, aX + c * KC, BZ * DS, tid);
            load_half(st + ST_B_HI, g_whi + WC_OFF, bC + c * KC, DS, tid);
            load_half(st + ST_B_LO, g_wlo + WC_OFF, bC + c * KC, DS, tid);
        } else {
            int k0 = (c - NC1) * KC;
            load_half(st + ST_A_HI, g_uhi, aU + k0, DI, tid);
            load_half(st + ST_A_LO, g_ulo, aU + k0, DI, tid);
            load_half(st + ST_B_HI, g_whi + WD_OFF, bD + k0, DI, tid);
            load_half(st + ST_B_LO, g_wlo + WD_OFF, bD + k0, DI, tid);
        }
        CP_COMMIT();
    };

    issue(0, sb);
    for (int c = 0; c < NC; c++) {
        if (c + 1 < NC) {
            issue(c + 1, sb + ((c + 1) & 1) * STAGE_BYTES);
            CP_WAIT1();
        } else {
            CP_WAIT0();
        }
        __syncthreads();
        char* sm = smem + (c & 1) * STAGE_BYTES;
        COMPUTE_CHUNK(sm);
        __syncthreads();
    }

    // epilogue: acc (m=l, n=o) -> smem transpose -> Y[b][o][l] (l contiguous)
    float* stg = (float*)smem;                       // [128][136] fp32 = 69632 B
    #pragma unroll
    for (int i = 0; i < 2; i++)
        #pragma unroll
        for (int j = 0; j < 4; j++) {
            float* sp = stg + (size_t)(wm * 32 + i * 16) * 136 + wn * 64 + j * 16;
            wmma::store_matrix_sync(sp, acc[i][j], 136, wmma::mem_row_major);
        }
    __syncthreads();
    {
        const int o = tid >> 1;                      // 0..127
        const int half = tid & 1;                    // l segment of 64
        float* yp = Y + ((size_t)b * DO + o0 + o) * LL + l0 + half * 64;
        const float* sp = stg + (size_t)(half * 64) * 136 + o;
        #pragma unroll
        for (int q = 0; q < 16; q++) {
            float4 v = make_float4(sp[(q * 4 + 0) * 136], sp[(q * 4 + 1) * 136],
                                   sp[(q * 4 + 2) * 136], sp[(q * 4 + 3) * 136]);
            *(float4*)(yp + q * 4) = v;
        }
    }
}

// ---------------- scan ----------------
__global__ __launch_bounds__(256) void scanA_kernel(const float* __restrict__ Aun) {
    const int t = blockIdx.x * 256 + threadIdx.x;
    const int lane = t & (LANES - 1);
    const int c = t >> 12;
    const int s = lane & (DS - 1);
    const float A = -softplus_f(Aun[s]);
    const float* g = g_Bu + (size_t)(c * CLEN) * LANES + lane;
    float x = 0.f;
    #pragma unroll 8
    for (int j = 0; j < CLEN; j++) x = fmaf(A, x, g[(size_t)j * LANES]);
    g_last[t] = x;
}

__global__ __launch_bounds__(256) void scanB_kernel(const float* __restrict__ Aun,
                                                    const float* __restrict__ h0) {
    const int lane = blockIdx.x * 256 + threadIdx.x;
    const int s = lane & (DS - 1);
    const float A = -softplus_f(Aun[s]);
    float Ap = A;
    #pragma unroll
    for (int i = 0; i < 7; i++) Ap *= Ap;
    float h = h0[s];
    #pragma unroll
    for (int c = 0; c < NCH; c++) {
        g_carry[c * LANES + lane] = h;
        h = fmaf(Ap, h, g_last[c * LANES + lane]);
    }
}

// scanC: rescan with correct carry; emit bf16 hi/lo split of x directly.
__global__ __launch_bounds__(256) void scanC_kernel(const float* __restrict__ Aun) {
    const int t = blockIdx.x * 256 + threadIdx.x;
    const int lane = t & (LANES - 1);
    const int c = t >> 12;
    const int s = lane & (DS - 1);
    const float A = -softplus_f(Aun[s]);
    float x = g_carry[t];
    const float* g = g_Bu + (size_t)(c * CLEN) * LANES + lane;
    __nv_bfloat16* xh = g_xhi + (size_t)(c * CLEN) * LANES + lane;
    __nv_bfloat16* xl = g_xlo + (size_t)(c * CLEN) * LANES + lane;
    #pragma unroll 4
    for (int j = 0; j < CLEN; j++) {
        x = fmaf(A, x, g[(size_t)j * LANES]);
        __nv_bfloat16 h = __float2bfloat16(x);
        xh[(size_t)j * LANES] = h;
        xl[(size_t)j * LANES] = __float2bfloat16(x - __bfloat162float(h));
    }
}

// ---------------- launch ----------------
extern "C" void kernel_launch(void* const* d_in, const int* in_sizes, int n_in,
                              void* d_out, int out_size) {
    const float* u   = (const float*)d_in[0];
    const float* Aun = (const float*)d_in[1];
    const float* Bm  = (const float*)d_in[2];
    const float* Cm  = (const float*)d_in[3];
    const float* Dm  = (const float*)d_in[4];
    const float* h0  = (const float*)d_in[5];
    float* Y = (float*)d_out;

    cudaFuncSetAttribute(gemm1_wmma, cudaFuncAttributeMaxDynamicSharedMemorySize, SMEM_BYTES);
    cudaFuncSetAttribute(gemm2_wmma, cudaFuncAttributeMaxDynamicSharedMemorySize, SMEM_BYTES);

    prep_kernel<<<(WTOT + 255) / 256, 256>>>(Bm, Cm, Dm);

    dim3 gu(LL / 32, DI / 32, BZ);
    usplit_kernel<<<gu, 256>>>(u);

    dim3 g1(LL / 128, DS / 128, BZ);
    gemm1_wmma<<<g1, 256, SMEM_BYTES>>>(0);

    scanA_kernel<<<(NCH * LANES) / 256, 256>>>(Aun);
    scanB_kernel<<<LANES / 256, 256>>>(Aun, h0);
    scanC_kernel<<<(NCH * LANES) / 256, 256>>>(Aun);

    dim3 g2(LL / 128, DO / 128, BZ);
    gemm2_wmma<<<g2, 256, SMEM_BYTES>>>(Y);
}

// round 10
// speedup vs baseline: 5.7161x; 2.0711x over previous
#include <cuda_runtime.h>
#include <cuda_fp16.h>
#include <mma.h>
#include <cstdint>
#include <math.h>

using namespace nvcuda;

// Problem constants
#define BZ   8
#define DI   256
#define DS   512
#define DO   256
#define LL   4096
#define NCH  32
#define CLEN 128
#define LANES (BZ*DS)

// ---------------- scratch ----------------
__device__ float g_Bu[(size_t)LL * BZ * DS];      // (l, b, s) fp32
__device__ float g_last[NCH * LANES];
__device__ float g_carry[NCH * LANES];
__device__ int   g_Dnz;                           // any(D != 0)

// fp16 operands
__device__ __half g_uh[(size_t)BZ * LL * DI];     // [b][l][i]
__device__ __half g_xh[(size_t)LL * BZ * DS];     // [l][b][s]

// fp16 weights, row-major [n][k]
#define WB_OFF 0
#define WC_OFF (512*256)
#define WD_OFF (WC_OFF + 256*512)
#define WTOT   (WD_OFF + 256*256)
__device__ __half g_wh[WTOT];

__device__ __forceinline__ float softplus_f(float x) {
    return fmaxf(x, 0.f) + log1pf(expf(-fabsf(x)));
}

// ---------------- cp.async helpers ----------------
__device__ __forceinline__ void cp16(uint32_t saddr, const void* g) {
    asm volatile("cp.async.cg.shared.global [%0], [%1], 16;" :: "r"(saddr), "l"(g));
}
#define CP_COMMIT() asm volatile("cp.async.commit_group;" ::: "memory")
#define CP_WAIT1()  asm volatile("cp.async.wait_group 1;" ::: "memory")
#define CP_WAIT0()  asm volatile("cp.async.wait_group 0;" ::: "memory")

// ---------------- smem layout ----------------
#define KC 64
#define LDS_T 72                          // padded ld (elements): 144B rows
#define ST_A 0
#define ST_B 18432                        // 128 * 144
#define STAGE_BYTES 36864
#define SMEM_BYTES (2 * STAGE_BYTES)      // 73728

// Copy one 128-row x 64-col fp16 tile into padded smem.
__device__ __forceinline__ void load_tile(uint32_t sbase, const __half* __restrict__ src,
                                          size_t gbase, int gstride, int tid) {
    const int row = tid >> 1, seg = tid & 1;
    const uint32_t sa = sbase + row * (LDS_T * 2) + seg * 64;
    const __half* gp = src + gbase + (size_t)row * gstride + seg * 32;
    cp16(sa,      gp);
    cp16(sa + 16, gp + 8);
    cp16(sa + 32, gp + 16);
    cp16(sa + 48, gp + 24);
}

// ---------------- prep ----------------
__global__ void zflag_kernel() { g_Dnz = 0; }

__global__ void prep_kernel(const float* __restrict__ Bm, const float* __restrict__ Cm,
                            const float* __restrict__ Dm) {
    int i = blockIdx.x * 256 + threadIdx.x;
    if (i >= WTOT) return;
    float v = (i < WC_OFF) ? Bm[i] : (i < WD_OFF ? Cm[i - WC_OFF] : Dm[i - WD_OFF]);
    g_wh[i] = __float2half_rn(v);
    if (i >= WD_OFF) {
        unsigned any = __ballot_sync(__activemask(), v != 0.f);
        if ((threadIdx.x & 31) == 0 && any) atomicOr(&g_Dnz, 1);
    }
}

// ---------------- usplit: u[b][i][l] -> fp16 [b][l][i] ----------------
__global__ __launch_bounds__(256) void usplit_kernel(const float* __restrict__ u) {
    __shared__ float t[32][33];
    const int tx = threadIdx.x & 31, ty = threadIdx.x >> 5;
    const int l0 = blockIdx.x * 32, i0 = blockIdx.y * 32, b = blockIdx.z;
    #pragma unroll
    for (int q = 0; q < 4; q++)
        t[ty + 8 * q][tx] = u[((size_t)b * DI + i0 + ty + 8 * q) * LL + l0 + tx];
    __syncthreads();
    #pragma unroll
    for (int q = 0; q < 4; q++) {
        const int l = l0 + ty + 8 * q;
        g_uh[((size_t)b * LL + l) * DI + i0 + tx] = __float2half_rn(t[tx][ty + 8 * q]);
    }
}

// ---------------- GEMM compute body ----------------
#define COMPUTE_CHUNK(sm)                                                                 \
    do {                                                                                  \
        __half* As = (__half*)((sm) + ST_A);                                              \
        __half* Bs = (__half*)((sm) + ST_B);                                              \
        _Pragma("unroll")                                                                 \
        for (int ks = 0; ks < KC; ks += 16) {                                             \
            wmma::fragment<wmma::matrix_a, 16, 16, 16, __half, wmma::row_major> af[2];    \
            _Pragma("unroll")                                                             \
            for (int i = 0; i < 2; i++)                                                   \
                wmma::load_matrix_sync(af[i], As + (wm * 32 + i * 16) * LDS_T + ks, LDS_T);\
            _Pragma("unroll")                                                             \
            for (int j = 0; j < 4; j++) {                                                 \
                wmma::fragment<wmma::matrix_b, 16, 16, 16, __half, wmma::col_major> bf;   \
                wmma::load_matrix_sync(bf, Bs + (wn * 64 + j * 16) * LDS_T + ks, LDS_T);  \
                _Pragma("unroll")                                                         \
                for (int i = 0; i < 2; i++)                                               \
                    wmma::mma_sync(acc[i][j], af[i], bf, acc[i][j]);                      \
            }                                                                             \
        }                                                                                 \
    } while (0)

// ---------------- GEMM1: g_Bu[l][b][s] = u . B^T ----------------
__global__ __launch_bounds__(256) void gemm1_wmma(int dummy) {
    extern __shared__ char smem[];
    const uint32_t sb = (uint32_t)__cvta_generic_to_shared(smem);
    const int tid = threadIdx.x, wid = tid >> 5;
    const int l0 = blockIdx.x * 128, n0 = blockIdx.y * 128, b = blockIdx.z;
    const int wm = wid & 3, wn = wid >> 2;

    wmma::fragment<wmma::accumulator, 16, 16, 16, float> acc[2][4];
    #pragma unroll
    for (int i = 0; i < 2; i++)
        #pragma unroll
        for (int j = 0; j < 4; j++) wmma::fill_fragment(acc[i][j], 0.f);

    const size_t aB = ((size_t)b * LL + l0) * DI;
    const size_t bB = (size_t)n0 * DI;
    const int NC = DI / KC;   // 4

    load_tile(sb + ST_A, g_uh, aB, DI, tid);
    load_tile(sb + ST_B, g_wh + WB_OFF, bB, DI, tid);
    CP_COMMIT();

    for (int c = 0; c < NC; c++) {
        if (c + 1 < NC) {
            uint32_t st = sb + ((c + 1) & 1) * STAGE_BYTES;
            load_tile(st + ST_A, g_uh, aB + (c + 1) * KC, DI, tid);
            load_tile(st + ST_B, g_wh + WB_OFF, bB + (c + 1) * KC, DI, tid);
            CP_COMMIT();
            CP_WAIT1();
        } else {
            CP_WAIT0();
        }
        __syncthreads();
        COMPUTE_CHUNK(smem + (c & 1) * STAGE_BYTES);
        __syncthreads();
    }

    #pragma unroll
    for (int i = 0; i < 2; i++)
        #pragma unroll
        for (int j = 0; j < 4; j++) {
            float* out = g_Bu + (size_t)(l0 + wm * 32 + i * 16) * (BZ * DS)
                              + (size_t)b * DS + n0 + wn * 64 + j * 16;
            wmma::store_matrix_sync(out, acc[i][j], BZ * DS, wmma::mem_row_major);
        }
}

// ---------------- GEMM2: Y[b][o][l] = C.x (+ D.u if D != 0) ----------------
__global__ __launch_bounds__(256) void gemm2_wmma(float* __restrict__ Y) {
    extern __shared__ char smem[];
    const uint32_t sb = (uint32_t)__cvta_generic_to_shared(smem);
    const int tid = threadIdx.x, wid = tid >> 5;
    const int l0 = blockIdx.x * 128, o0 = blockIdx.y * 128, b = blockIdx.z;
    const int wm = wid & 3, wn = wid >> 2;

    wmma::fragment<wmma::accumulator, 16, 16, 16, float> acc[2][4];
    #pragma unroll
    for (int i = 0; i < 2; i++)
        #pragma unroll
        for (int j = 0; j < 4; j++) wmma::fill_fragment(acc[i][j], 0.f);

    const size_t aX = ((size_t)l0 * BZ + b) * DS;    // x base, row stride BZ*DS
    const size_t aU = ((size_t)b * LL + l0) * DI;    // u base, row stride DI
    const size_t bC = (size_t)o0 * DS;
    const size_t bD = (size_t)o0 * DI;
    const int NC1 = DS / KC;                         // 8
    const int NC = NC1 + (g_Dnz ? DI / KC : 0);      // 8 or 12

    auto issue = [&](int c, uint32_t st) {
        if (c < NC1) {
            load_tile(st + ST_A, g_xh, aX + c * KC, BZ * DS, tid);
            load_tile(st + ST_B, g_wh + WC_OFF, bC + c * KC, DS, tid);
        } else {
            int k0 = (c - NC1) * KC;
            load_tile(st + ST_A, g_uh, aU + k0, DI, tid);
            load_tile(st + ST_B, g_wh + WD_OFF, bD + k0, DI, tid);
        }
        CP_COMMIT();
    };

    issue(0, sb);
    for (int c = 0; c < NC; c++) {
        if (c + 1 < NC) {
            issue(c + 1, sb + ((c + 1) & 1) * STAGE_BYTES);
            CP_WAIT1();
        } else {
            CP_WAIT0();
        }
        __syncthreads();
        COMPUTE_CHUNK(smem + (c & 1) * STAGE_BYTES);
        __syncthreads();
    }

    // epilogue: acc (m=l, n=o) -> smem transpose -> Y[b][o][l] (l contiguous)
    float* stg = (float*)smem;                       // [128][136] fp32 = 69632 B
    #pragma unroll
    for (int i = 0; i < 2; i++)
        #pragma unroll
        for (int j = 0; j < 4; j++) {
            float* sp = stg + (size_t)(wm * 32 + i * 16) * 136 + wn * 64 + j * 16;
            wmma::store_matrix_sync(sp, acc[i][j], 136, wmma::mem_row_major);
        }
    __syncthreads();
    {
        const int o = tid >> 1;                      // 0..127
        const int half = tid & 1;
        float* yp = Y + ((size_t)b * DO + o0 + o) * LL + l0 + half * 64;
        const float* sp = stg + (size_t)(half * 64) * 136 + o;
        #pragma unroll
        for (int q = 0; q < 16; q++) {
            float4 v = make_float4(sp[(q * 4 + 0) * 136], sp[(q * 4 + 1) * 136],
                                   sp[(q * 4 + 2) * 136], sp[(q * 4 + 3) * 136]);
            *(float4*)(yp + q * 4) = v;
        }
    }
}

// ---------------- scan ----------------
__global__ __launch_bounds__(256) void scanA_kernel(const float* __restrict__ Aun) {
    const int t = blockIdx.x * 256 + threadIdx.x;
    const int lane = t & (LANES - 1);
    const int c = t >> 12;
    const int s = lane & (DS - 1);
    const float A = -softplus_f(Aun[s]);
    const float* g = g_Bu + (size_t)(c * CLEN) * LANES + lane;
    float x = 0.f;
    #pragma unroll 8
    for (int j = 0; j < CLEN; j++) x = fmaf(A, x, g[(size_t)j * LANES]);
    g_last[t] = x;
}

__global__ __launch_bounds__(256) void scanB_kernel(const float* __restrict__ Aun,
                                                    const float* __restrict__ h0) {
    const int lane = blockIdx.x * 256 + threadIdx.x;
    const int s = lane & (DS - 1);
    const float A = -softplus_f(Aun[s]);
    float Ap = A;
    #pragma unroll
    for (int i = 0; i < 7; i++) Ap *= Ap;
    float h = h0[s];
    #pragma unroll
    for (int c = 0; c < NCH; c++) {
        g_carry[c * LANES + lane] = h;
        h = fmaf(Ap, h, g_last[c * LANES + lane]);
    }
}

// scanC: rescan with correct carry; emit fp16 x directly.
__global__ __launch_bounds__(256) void scanC_kernel(const float* __restrict__ Aun) {
    const int t = blockIdx.x * 256 + threadIdx.x;
    const int lane = t & (LANES - 1);
    const int c = t >> 12;
    const int s = lane & (DS - 1);
    const float A = -softplus_f(Aun[s]);
    float x = g_carry[t];
    const float* g = g_Bu + (size_t)(c * CLEN) * LANES + lane;
    __half* xh = g_xh + (size_t)(c * CLEN) * LANES + lane;
    #pragma unroll 4
    for (int j = 0; j < CLEN; j++) {
        x = fmaf(A, x, g[(size_t)j * LANES]);
        xh[(size_t)j * LANES] = __float2half_rn(x);
    }
}

// ---------------- launch ----------------
extern "C" void kernel_launch(void* const* d_in, const int* in_sizes, int n_in,
                              void* d_out, int out_size) {
    const float* u   = (const float*)d_in[0];
    const float* Aun = (const float*)d_in[1];
    const float* Bm  = (const float*)d_in[2];
    const float* Cm  = (const float*)d_in[3];
    const float* Dm  = (const float*)d_in[4];
    const float* h0  = (const float*)d_in[5];
    float* Y = (float*)d_out;

    cudaFuncSetAttribute(gemm1_wmma, cudaFuncAttributeMaxDynamicSharedMemorySize, SMEM_BYTES);
    cudaFuncSetAttribute(gemm2_wmma, cudaFuncAttributeMaxDynamicSharedMemorySize, SMEM_BYTES);

    zflag_kernel<<<1, 1>>>();
    prep_kernel<<<(WTOT + 255) / 256, 256>>>(Bm, Cm, Dm);

    dim3 gu(LL / 32, DI / 32, BZ);
    usplit_kernel<<<gu, 256>>>(u);

    dim3 g1(LL / 128, DS / 128, BZ);
    gemm1_wmma<<<g1, 256, SMEM_BYTES>>>(0);

    scanA_kernel<<<(NCH * LANES) / 256, 256>>>(Aun);
    scanB_kernel<<<LANES / 256, 256>>>(Aun, h0);
    scanC_kernel<<<(NCH * LANES) / 256, 256>>>(Aun);

    dim3 g2(LL / 128, DO / 128, BZ);
    gemm2_wmma<<<g2, 256, SMEM_BYTES>>>(Y);
}

// round 11
// speedup vs baseline: 6.0012x; 1.0499x over previous
#include <cuda_runtime.h>
#include <cuda_fp16.h>
#include <mma.h>
#include <cstdint>
#include <math.h>

using namespace nvcuda;

// Problem constants
#define BZ   8
#define DI   256
#define DS   512
#define DO   256
#define LL   4096
#define NCH  32
#define CLEN 128
#define LANES (BZ*DS)

// ---------------- scratch ----------------
__device__ float g_Bu[(size_t)LL * BZ * DS];      // (l, b, s) fp32
__device__ float g_last[NCH * LANES];
__device__ float g_carry[NCH * LANES];
__device__ int   g_Dnz;                           // any(D != 0)

// fp16 operands
__device__ __half g_uh[(size_t)BZ * LL * DI];     // [b][l][i]
__device__ __half g_xh[(size_t)LL * BZ * DS];     // [l][b][s]

// fp16 weights, row-major [n][k]
#define WB_OFF 0
#define WC_OFF (512*256)
#define WD_OFF (WC_OFF + 256*512)
#define WTOT   (WD_OFF + 256*256)
__device__ __half g_wh[WTOT];

__device__ __forceinline__ float softplus_f(float x) {
    return fmaxf(x, 0.f) + log1pf(expf(-fabsf(x)));
}

// ---------------- cp.async helpers ----------------
__device__ __forceinline__ void cp16(uint32_t saddr, const void* g) {
    asm volatile("cp.async.cg.shared.global [%0], [%1], 16;" :: "r"(saddr), "l"(g));
}
#define CP_COMMIT() asm volatile("cp.async.commit_group;" ::: "memory")
#define CP_WAIT2()  asm volatile("cp.async.wait_group 2;" ::: "memory")

// ---------------- smem layout: 4-stage ring, KC=32 ----------------
#define KC 32
#define NSTG 4
#define LDS_T 40                          // padded ld (elements): 80B rows
#define ST_A 0
#define ST_B 10240                        // 128 * 80
#define STAGE_BYTES 20480
#define SMEM_BYTES (NSTG * STAGE_BYTES)   // 81920

// Copy one 128-row x 32-col fp16 tile into padded smem (2 threads/row).
__device__ __forceinline__ void load_tile(uint32_t sbase, const __half* __restrict__ src,
                                          size_t gbase, int gstride, int tid) {
    const int row = tid >> 1, seg = tid & 1;
    const uint32_t sa = sbase + row * (LDS_T * 2) + seg * 32;
    const __half* gp = src + gbase + (size_t)row * gstride + seg * 16;
    cp16(sa, gp);
    cp16(sa + 16, gp + 8);
}

// ---------------- prep ----------------
__global__ void zflag_kernel() { g_Dnz = 0; }

__global__ void prep_kernel(const float* __restrict__ Bm, const float* __restrict__ Cm,
                            const float* __restrict__ Dm) {
    int i = blockIdx.x * 256 + threadIdx.x;
    if (i >= WTOT) return;
    float v = (i < WC_OFF) ? Bm[i] : (i < WD_OFF ? Cm[i - WC_OFF] : Dm[i - WD_OFF]);
    g_wh[i] = __float2half_rn(v);
    if (i >= WD_OFF) {
        unsigned any = __ballot_sync(__activemask(), v != 0.f);
        if ((threadIdx.x & 31) == 0 && any) atomicOr(&g_Dnz, 1);
    }
}

// ---------------- usplit: u[b][i][l] -> fp16 [b][l][i] ----------------
__global__ __launch_bounds__(256) void usplit_kernel(const float* __restrict__ u) {
    __shared__ float t[32][33];
    const int tx = threadIdx.x & 31, ty = threadIdx.x >> 5;
    const int l0 = blockIdx.x * 32, i0 = blockIdx.y * 32, b = blockIdx.z;
    #pragma unroll
    for (int q = 0; q < 4; q++)
        t[ty + 8 * q][tx] = u[((size_t)b * DI + i0 + ty + 8 * q) * LL + l0 + tx];
    __syncthreads();
    #pragma unroll
    for (int q = 0; q < 4; q++) {
        const int l = l0 + ty + 8 * q;
        g_uh[((size_t)b * LL + l) * DI + i0 + tx] = __float2half_rn(t[tx][ty + 8 * q]);
    }
}

// ---------------- GEMM compute body (one KC=32 chunk) ----------------
#define COMPUTE_CHUNK(sm)                                                                 \
    do {                                                                                  \
        __half* As = (__half*)((sm) + ST_A);                                              \
        __half* Bs = (__half*)((sm) + ST_B);                                              \
        _Pragma("unroll")                                                                 \
        for (int ks = 0; ks < KC; ks += 16) {                                             \
            wmma::fragment<wmma::matrix_a, 16, 16, 16, __half, wmma::row_major> af[2];    \
            _Pragma("unroll")                                                             \
            for (int i = 0; i < 2; i++)                                                   \
                wmma::load_matrix_sync(af[i], As + (wm * 32 + i * 16) * LDS_T + ks, LDS_T);\
            _Pragma("unroll")                                                             \
            for (int j = 0; j < 4; j++) {                                                 \
                wmma::fragment<wmma::matrix_b, 16, 16, 16, __half, wmma::col_major> bf;   \
                wmma::load_matrix_sync(bf, Bs + (wn * 64 + j * 16) * LDS_T + ks, LDS_T);  \
                _Pragma("unroll")                                                         \
                for (int i = 0; i < 2; i++)                                               \
                    wmma::mma_sync(acc[i][j], af[i], bf, acc[i][j]);                      \
            }                                                                             \
        }                                                                                 \
    } while (0)

// ---------------- GEMM1: g_Bu[l][b][s] = u . B^T ----------------
__global__ __launch_bounds__(256) void gemm1_wmma(int dummy) {
    extern __shared__ char smem[];
    const uint32_t sb = (uint32_t)__cvta_generic_to_shared(smem);
    const int tid = threadIdx.x, wid = tid >> 5;
    const int l0 = blockIdx.x * 128, n0 = blockIdx.y * 128, b = blockIdx.z;
    const int wm = wid & 3, wn = wid >> 2;

    wmma::fragment<wmma::accumulator, 16, 16, 16, float> acc[2][4];
    #pragma unroll
    for (int i = 0; i < 2; i++)
        #pragma unroll
        for (int j = 0; j < 4; j++) wmma::fill_fragment(acc[i][j], 0.f);

    const size_t aB = ((size_t)b * LL + l0) * DI;
    const size_t bB = (size_t)n0 * DI;
    const int NC = DI / KC;   // 8

    // prologue: stages 0..NSTG-2
    #pragma unroll
    for (int s = 0; s < NSTG - 1; s++) {
        uint32_t st = sb + s * STAGE_BYTES;
        load_tile(st + ST_A, g_uh, aB + s * KC, DI, tid);
        load_tile(st + ST_B, g_wh + WB_OFF, bB + s * KC, DI, tid);
        CP_COMMIT();
    }

    for (int c = 0; c < NC; c++) {
        CP_WAIT2();                // stage c landed
        __syncthreads();           // all warps done with compute(c-1); stage (c-1)%4 free
        int nc = c + NSTG - 1;
        if (nc < NC) {
            uint32_t st = sb + (nc % NSTG) * STAGE_BYTES;
            load_tile(st + ST_A, g_uh, aB + nc * KC, DI, tid);
            load_tile(st + ST_B, g_wh + WB_OFF, bB + nc * KC, DI, tid);
        }
        CP_COMMIT();               // (possibly empty) keeps group count aligned
        COMPUTE_CHUNK(smem + (c % NSTG) * STAGE_BYTES);
    }

    #pragma unroll
    for (int i = 0; i < 2; i++)
        #pragma unroll
        for (int j = 0; j < 4; j++) {
            float* out = g_Bu + (size_t)(l0 + wm * 32 + i * 16) * (BZ * DS)
                              + (size_t)b * DS + n0 + wn * 64 + j * 16;
            wmma::store_matrix_sync(out, acc[i][j], BZ * DS, wmma::mem_row_major);
        }
}

// ---------------- GEMM2: Y[b][o][l] = C.x (+ D.u if D != 0) ----------------
__global__ __launch_bounds__(256) void gemm2_wmma(float* __restrict__ Y) {
    extern __shared__ char smem[];
    const uint32_t sb = (uint32_t)__cvta_generic_to_shared(smem);
    const int tid = threadIdx.x, wid = tid >> 5;
    const int l0 = blockIdx.x * 128, o0 = blockIdx.y * 128, b = blockIdx.z;
    const int wm = wid & 3, wn = wid >> 2;

    wmma::fragment<wmma::accumulator, 16, 16, 16, float> acc[2][4];
    #pragma unroll
    for (int i = 0; i < 2; i++)
        #pragma unroll
        for (int j = 0; j < 4; j++) wmma::fill_fragment(acc[i][j], 0.f);

    const size_t aX = ((size_t)l0 * BZ + b) * DS;    // x base, row stride BZ*DS
    const size_t aU = ((size_t)b * LL + l0) * DI;    // u base, row stride DI
    const size_t bC = (size_t)o0 * DS;
    const size_t bD = (size_t)o0 * DI;
    const int NC1 = DS / KC;                         // 16
    const int NC = NC1 + (g_Dnz ? DI / KC : 0);      // 16 or 24

    auto issue = [&](int c, uint32_t st) {
        if (c < NC1) {
            load_tile(st + ST_A, g_xh, aX + c * KC, BZ * DS, tid);
            load_tile(st + ST_B, g_wh + WC_OFF, bC + c * KC, DS, tid);
        } else {
            int k0 = (c - NC1) * KC;
            load_tile(st + ST_A, g_uh, aU + k0, DI, tid);
            load_tile(st + ST_B, g_wh + WD_OFF, bD + k0, DI, tid);
        }
    };

    #pragma unroll
    for (int s = 0; s < NSTG - 1; s++) {
        issue(s, sb + s * STAGE_BYTES);
        CP_COMMIT();
    }

    for (int c = 0; c < NC; c++) {
        CP_WAIT2();
        __syncthreads();
        int nc = c + NSTG - 1;
        if (nc < NC) issue(nc, sb + (nc % NSTG) * STAGE_BYTES);
        CP_COMMIT();
        COMPUTE_CHUNK(smem + (c % NSTG) * STAGE_BYTES);
    }

    // epilogue: acc (m=l, n=o) -> smem transpose -> Y[b][o][l] (l contiguous)
    __syncthreads();
    float* stg = (float*)smem;                       // [128][136] fp32 = 69632 B
    #pragma unroll
    for (int i = 0; i < 2; i++)
        #pragma unroll
        for (int j = 0; j < 4; j++) {
            float* sp = stg + (size_t)(wm * 32 + i * 16) * 136 + wn * 64 + j * 16;
            wmma::store_matrix_sync(sp, acc[i][j], 136, wmma::mem_row_major);
        }
    __syncthreads();
    {
        const int o = tid >> 1;                      // 0..127
        const int half = tid & 1;
        float* yp = Y + ((size_t)b * DO + o0 + o) * LL + l0 + half * 64;
        const float* sp = stg + (size_t)(half * 64) * 136 + o;
        #pragma unroll
        for (int q = 0; q < 16; q++) {
            float4 v = make_float4(sp[(q * 4 + 0) * 136], sp[(q * 4 + 1) * 136],
                                   sp[(q * 4 + 2) * 136], sp[(q * 4 + 3) * 136]);
            *(float4*)(yp + q * 4) = v;
        }
    }
}

// ---------------- scan: 4 lanes per thread ----------------
__global__ __launch_bounds__(256) void scanA_kernel(const float* __restrict__ Aun) {
    const int t = blockIdx.x * 256 + threadIdx.x;       // 0..NCH*LANES/4-1
    const int lane4 = (t & (LANES / 4 - 1)) * 4;
    const int c = t / (LANES / 4);
    const int s = lane4 & (DS - 1);
    float4 Av = make_float4(-softplus_f(Aun[s]), -softplus_f(Aun[s + 1]),
                            -softplus_f(Aun[s + 2]), -softplus_f(Aun[s + 3]));
    const float* g = g_Bu + (size_t)(c * CLEN) * LANES + lane4;
    float4 x = make_float4(0.f, 0.f, 0.f, 0.f);
    #pragma unroll 8
    for (int j = 0; j < CLEN; j++) {
        float4 v = *(const float4*)(g + (size_t)j * LANES);
        x.x = fmaf(Av.x, x.x, v.x);
        x.y = fmaf(Av.y, x.y, v.y);
        x.z = fmaf(Av.z, x.z, v.z);
        x.w = fmaf(Av.w, x.w, v.w);
    }
    *(float4*)(g_last + (size_t)c * LANES + lane4) = x;
}

__global__ __launch_bounds__(256) void scanB_kernel(const float* __restrict__ Aun,
                                                    const float* __restrict__ h0) {
    const int lane = blockIdx.x * 256 + threadIdx.x;
    const int s = lane & (DS - 1);
    const float A = -softplus_f(Aun[s]);
    float Ap = A;
    #pragma unroll
    for (int i = 0; i < 7; i++) Ap *= Ap;
    // preload all chunk-lasts with independent loads (MLP=32)
    float lastv[NCH];
    #pragma unroll
    for (int c = 0; c < NCH; c++) lastv[c] = g_last[c * LANES + lane];
    float h = h0[s];
    #pragma unroll
    for (int c = 0; c < NCH; c++) {
        g_carry[c * LANES + lane] = h;
        h = fmaf(Ap, h, lastv[c]);
    }
}

// scanC: rescan with correct carry; emit fp16 x directly (4 lanes/thread).
__global__ __launch_bounds__(256) void scanC_kernel(const float* __restrict__ Aun) {
    const int t = blockIdx.x * 256 + threadIdx.x;
    const int lane4 = (t & (LANES / 4 - 1)) * 4;
    const int c = t / (LANES / 4);
    const int s = lane4 & (DS - 1);
    float4 Av = make_float4(-softplus_f(Aun[s]), -softplus_f(Aun[s + 1]),
                            -softplus_f(Aun[s + 2]), -softplus_f(Aun[s + 3]));
    float4 x = *(const float4*)(g_carry + (size_t)c * LANES + lane4);
    const float* g = g_Bu + (size_t)(c * CLEN) * LANES + lane4;
    __half* xh = g_xh + (size_t)(c * CLEN) * LANES + lane4;
    #pragma unroll 4
    for (int j = 0; j < CLEN; j++) {
        float4 v = *(const float4*)(g + (size_t)j * LANES);
        x.x = fmaf(Av.x, x.x, v.x);
        x.y = fmaf(Av.y, x.y, v.y);
        x.z = fmaf(Av.z, x.z, v.z);
        x.w = fmaf(Av.w, x.w, v.w);
        __half2 p0 = __floats2half2_rn(x.x, x.y);
        __half2 p1 = __floats2half2_rn(x.z, x.w);
        uint2 pk = make_uint2(*(uint32_t*)&p0, *(uint32_t*)&p1);
        *(uint2*)(xh + (size_t)j * LANES) = pk;
    }
}

// ---------------- launch ----------------
extern "C" void kernel_launch(void* const* d_in, const int* in_sizes, int n_in,
                              void* d_out, int out_size) {
    const float* u   = (const float*)d_in[0];
    const float* Aun = (const float*)d_in[1];
    const float* Bm  = (const float*)d_in[2];
    const float* Cm  = (const float*)d_in[3];
    const float* Dm  = (const float*)d_in[4];
    const float* h0  = (const float*)d_in[5];
    float* Y = (float*)d_out;

    cudaFuncSetAttribute(gemm1_wmma, cudaFuncAttributeMaxDynamicSharedMemorySize, SMEM_BYTES);
    cudaFuncSetAttribute(gemm2_wmma, cudaFuncAttributeMaxDynamicSharedMemorySize, SMEM_BYTES);

    zflag_kernel<<<1, 1>>>();
    prep_kernel<<<(WTOT + 255) / 256, 256>>>(Bm, Cm, Dm);

    dim3 gu(LL / 32, DI / 32, BZ);
    usplit_kernel<<<gu, 256>>>(u);

    dim3 g1(LL / 128, DS / 128, BZ);
    gemm1_wmma<<<g1, 256, SMEM_BYTES>>>(0);

    scanA_kernel<<<(NCH * LANES / 4) / 256, 256>>>(Aun);
    scanB_kernel<<<LANES / 256, 256>>>(Aun, h0);
    scanC_kernel<<<(NCH * LANES / 4) / 256, 256>>>(Aun);

    dim3 g2(LL / 128, DO / 128, BZ);
    gemm2_wmma<<<g2, 256, SMEM_BYTES>>>(Y);
}